// round 16
// baseline (speedup 1.0000x reference)
#include <cuda_runtime.h>
#include <cuda_fp16.h>
#include <cstdint>

#define Bn 32
#define Cn 256
#define Tn 4096

// Static device scratch (allocation-guard legal).
__device__ float4   g_e4[(size_t)Bn * Cn * Cn / 4];      //  8 MB P = S + M (fp32)
__device__ float4   g_m4[(size_t)Bn * Cn * Cn / 4];      //  8 MB M = Xl*Xh^T (fp32)
__device__ uint32_t g_ah32[(size_t)Bn * Cn * Cn / 2];    //  4 MB attn hi (f16)
__device__ uint32_t g_xh32[(size_t)Bn * Cn * Tn / 2];    // 67 MB X hi  row-major
__device__ uint32_t g_xl32[(size_t)Bn * Cn * Tn / 2];    // 67 MB X lo  row-major
__device__ uint32_t g_xth32[(size_t)Bn * Tn * Cn / 2];   // 67 MB X^T hi

// ---------------------------------------------------------------------------
// Tile layout (proven): row = 64 k f16 = 128 B = 32 words; 16B group g at
// word offset row*32 + (g^(row&7))*4. cp.async / LDSM conflict-free.
// ---------------------------------------------------------------------------
__device__ __forceinline__ int woff(int row, int g) {
    return row * 32 + ((g ^ (row & 7)) << 2);
}
__device__ __forceinline__ uint32_t smem_u32(const void* p) {
    uint32_t a;
    asm("{ .reg .u64 t; cvta.to.shared.u64 t, %1; cvt.u32.u64 %0, t; }"
        : "=r"(a) : "l"(p));
    return a;
}
__device__ __forceinline__ uint32_t packh2(__half a, __half b) {
    return (uint32_t)__half_as_ushort(a) | ((uint32_t)__half_as_ushort(b) << 16);
}
__device__ __forceinline__ void mma_f16(float* d, const uint32_t* a, const uint32_t* b) {
    asm volatile(
        "mma.sync.aligned.m16n8k16.row.col.f32.f16.f16.f32 "
        "{%0,%1,%2,%3}, {%4,%5,%6,%7}, {%8,%9}, {%0,%1,%2,%3};"
        : "+f"(d[0]), "+f"(d[1]), "+f"(d[2]), "+f"(d[3])
        : "r"(a[0]), "r"(a[1]), "r"(a[2]), "r"(a[3]), "r"(b[0]), "r"(b[1]));
}
__device__ __forceinline__ void ldsm4(uint32_t& r0, uint32_t& r1, uint32_t& r2,
                                      uint32_t& r3, uint32_t addr) {
    asm volatile("ldmatrix.sync.aligned.m8n8.x4.shared.b16 {%0,%1,%2,%3}, [%4];"
                 : "=r"(r0), "=r"(r1), "=r"(r2), "=r"(r3) : "r"(addr));
}
__device__ __forceinline__ void lda_frag(uint32_t* a, uint32_t tb, int mrow,
                                         int ks, int lane) {
    int oct = lane >> 3, l7 = lane & 7;
    int row = mrow + ((oct & 1) << 3) + l7;
    int g = 2 * ks + (oct >> 1);
    ldsm4(a[0], a[1], a[2], a[3], tb + 4 * woff(row, g));
}
__device__ __forceinline__ void ldb_frag(uint32_t* b, uint32_t tb, int nrow,
                                         int ks, int lane) {
    int oct = lane >> 3, l7 = lane & 7;
    int row = nrow + ((oct >> 1) << 3) + l7;
    int g = 2 * ks + (oct & 1);
    ldsm4(b[0], b[1], b[2], b[3], tb + 4 * woff(row, g));
}
__device__ __forceinline__ void cp16(uint32_t saddr, const void* g) {
    asm volatile("cp.async.cg.shared.global [%0], [%1], 16;" :: "r"(saddr), "l"(g));
}
#define CP_COMMIT() asm volatile("cp.async.commit_group;" ::: "memory")
#define CP_WAIT(N)  asm volatile("cp.async.wait_group %0;" :: "n"(N) : "memory")

// ---------------------------------------------------------------------------
// Prepass (R14-proven): one read of X -> Xh (rm), Xl (rm), Xth, all f16.
// ---------------------------------------------------------------------------
__global__ __launch_bounds__(256) void split_pre(const float* __restrict__ x) {
    __shared__ __half tile[64][34];
    const int b = blockIdx.z, c0 = blockIdx.y * 32, t0 = blockIdx.x * 64;
    const int tid = threadIdx.x, cl = tid >> 5, t2 = tid & 31;
    const float* Xb = x + ((size_t)b * Cn + c0) * Tn + t0;
    uint32_t* Xh = g_xh32 + ((size_t)b * Cn + c0) * (Tn / 2) + t0 / 2;
    uint32_t* Xl = g_xl32 + ((size_t)b * Cn + c0) * (Tn / 2) + t0 / 2;
#pragma unroll
    for (int i = 0; i < 4; i++) {
        int c = cl + 8 * i;
        float2 v = *(const float2*)(Xb + (size_t)c * Tn + 2 * t2);
        __half h0 = __float2half_rn(v.x), h1 = __float2half_rn(v.y);
        Xh[(size_t)c * (Tn / 2) + t2] = packh2(h0, h1);
        Xl[(size_t)c * (Tn / 2) + t2] =
            packh2(__float2half_rn(v.x - __half2float(h0)),
                   __float2half_rn(v.y - __half2float(h1)));
        tile[2 * t2][c] = h0;
        tile[2 * t2 + 1][c] = h1;
    }
    __syncthreads();
    uint32_t* Xt = g_xth32 + ((size_t)b * Tn + t0) * (Cn / 2) + c0 / 2;
    const int tl = tid >> 4, c2 = tid & 15;
#pragma unroll
    for (int i = 0; i < 4; i++) {
        int t = tl + 16 * i;
        Xt[(size_t)t * (Cn / 2) + c2] = packh2(tile[t][2 * c2], tile[t][2 * c2 + 1]);
    }
}

// ---------------------------------------------------------------------------
// GEMM1 (symmetry trick): per tile compute S = Ah*Bh^T and M = Al*Bh^T only.
// E(i,j) = S(i,j) + M(i,j) + M(j,i) is assembled by softmax.
// CTA 128x128, 16 warps (32x32 tiles), BK=64, 3-stage cp.async.
// ---------------------------------------------------------------------------
__device__ __forceinline__ void g1_chunk(uint32_t sbase, float accS[8][4],
                                         float accM[8][4], int warpM, int warpN,
                                         int lane) {
    const uint32_t AH = sbase, AL = sbase + 4096 * 4, BH = sbase + 8192 * 4;
#pragma unroll
    for (int ks = 0; ks < 4; ks++) {
        uint32_t ah[2][4], al[2][4], bh[4][2];
#pragma unroll
        for (int ma = 0; ma < 2; ma++) lda_frag(ah[ma], AH, warpM + ma * 16, ks, lane);
#pragma unroll
        for (int ma = 0; ma < 2; ma++) lda_frag(al[ma], AL, warpM + ma * 16, ks, lane);
        ldb_frag(&bh[0][0], BH, warpN, ks, lane);
        ldb_frag(&bh[2][0], BH, warpN + 16, ks, lane);
#pragma unroll
        for (int ma = 0; ma < 2; ma++)
#pragma unroll
            for (int na = 0; na < 4; na++) {
                mma_f16(accS[ma * 4 + na], ah[ma], bh[na]);
                mma_f16(accM[ma * 4 + na], al[ma], bh[na]);
            }
    }
}

__global__ __launch_bounds__(512, 1) void gemm1_h() {
    extern __shared__ uint32_t sm[];
    const uint32_t sb = smem_u32(sm);
    const int tid = threadIdx.x, lane = tid & 31, wid = tid >> 5;
    const int gid = lane >> 2, tig = lane & 3;
    const int warpM = (wid >> 2) * 32, warpN = (wid & 3) * 32;
    const size_t pa = ((size_t)blockIdx.z * Cn + blockIdx.y * 128) * (Tn / 2);
    const size_t pb = ((size_t)blockIdx.z * Cn + blockIdx.x * 128) * (Tn / 2);
    const uint32_t* Ahp = g_xh32 + pa;
    const uint32_t* Alp = g_xl32 + pa;
    const uint32_t* Bhp = g_xh32 + pb;

    float accS[8][4], accM[8][4];
#pragma unroll
    for (int a = 0; a < 8; a++)
#pragma unroll
        for (int c = 0; c < 4; c++) { accS[a][c] = 0.f; accM[a][c] = 0.f; }

    auto issue = [&](int c, int s) {
        uint32_t st = sb + s * 12288 * 4;
#pragma unroll
        for (int it = 0; it < 2; it++) {
            int idx = it * 512 + tid, row = idx >> 3, g = idx & 7;
            int w4 = 4 * woff(row, g);
            size_t go = (size_t)row * (Tn / 2) + c * 32 + g * 4;
            cp16(st + w4, Ahp + go);
            cp16(st + 4096 * 4 + w4, Alp + go);
            cp16(st + 8192 * 4 + w4, Bhp + go);
        }
    };

    issue(0, 0); CP_COMMIT();
    issue(1, 1); CP_COMMIT();
    issue(2, 2); CP_COMMIT();
    CP_WAIT(2);
    __syncthreads();

    const int NC = Tn / 64;   // 64
#pragma unroll 1
    for (int c = 0; c < NC; c++) {
        g1_chunk(sb + (c % 3) * 12288 * 4, accS, accM, warpM, warpN, lane);
        if (c + 1 < NC) {
            __syncthreads();
            if (c + 3 < NC) issue(c + 3, c % 3);
            CP_COMMIT();
            CP_WAIT(2);
            __syncthreads();
        }
    }

    float* P = (float*)g_e4 + (size_t)blockIdx.z * Cn * Cn;
    float* Mm = (float*)g_m4 + (size_t)blockIdx.z * Cn * Cn;
#pragma unroll
    for (int ma = 0; ma < 2; ma++)
#pragma unroll
        for (int na = 0; na < 4; na++) {
            const float* s = accS[ma * 4 + na];
            const float* m = accM[ma * 4 + na];
            int r0 = blockIdx.y * 128 + warpM + ma * 16 + gid;
            int cc = blockIdx.x * 128 + warpN + na * 8 + 2 * tig;
            size_t o0 = (size_t)r0 * Cn + cc, o1 = (size_t)(r0 + 8) * Cn + cc;
            *(float2*)(P + o0) = make_float2(s[0] + m[0], s[1] + m[1]);
            *(float2*)(P + o1) = make_float2(s[2] + m[2], s[3] + m[3]);
            *(float2*)(Mm + o0) = make_float2(m[0], m[1]);
            *(float2*)(Mm + o1) = make_float2(m[2], m[3]);
        }
}

// ---------------------------------------------------------------------------
// Softmax: E(i,j) = P(i,j) + M(j,i); w = exp(min_e - e)/sum; writes f16 hi.
// ---------------------------------------------------------------------------
__global__ __launch_bounds__(256) void softmax_kernel() {
    const int row = blockIdx.x;               // b*Cn + i
    const int tid = threadIdx.x;
    const int i = row & (Cn - 1);
    const float* P = (float*)g_e4;
    const float* Mm = (float*)g_m4;

    float e = P[(size_t)row * Cn + tid] +
              Mm[((size_t)(row - i) + tid) * Cn + i];   // M(j=tid, i), batch base
    float v = e;
#pragma unroll
    for (int o = 16; o; o >>= 1) v = fminf(v, __shfl_xor_sync(0xffffffffu, v, o));
    __shared__ float red[8];
    __shared__ float bc[2];
    if ((tid & 31) == 0) red[tid >> 5] = v;
    __syncthreads();
    if (tid == 0) {
        float m = red[0];
#pragma unroll
        for (int k = 1; k < 8; k++) m = fminf(m, red[k]);
        bc[0] = m;
    }
    __syncthreads();
    float p = expf(bc[0] - e);
    v = p;
#pragma unroll
    for (int o = 16; o; o >>= 1) v += __shfl_xor_sync(0xffffffffu, v, o);
    if ((tid & 31) == 0) red[tid >> 5] = v;
    __syncthreads();
    if (tid == 0) {
        float s = 0.f;
#pragma unroll
        for (int k = 0; k < 8; k++) s += red[k];
        bc[1] = 1.0f / s;
    }
    __syncthreads();
    ((__half*)g_ah32)[(size_t)row * Cn + tid] = __float2half_rn(p * bc[1]);
}

// ---------------------------------------------------------------------------
// GEMM2: out = gamma*(Attn_h*X_h) + X. CTA 64x128 (m x n), 8 warps (32x32
// tiles), BK=64, 3-stage cp.async, 3 CTAs/SM (24 warps/SM — latency fix).
// Stage words: AH 0..2047 (64 rows), BH 2048..6143 (128 rows); stride 6144.
// ---------------------------------------------------------------------------
__device__ __forceinline__ void g2_chunk(uint32_t sbase, float acc[8][4],
                                         int warpM, int warpN, int lane) {
    const uint32_t AH = sbase, BH = sbase + 2048 * 4;
#pragma unroll
    for (int ks = 0; ks < 4; ks++) {
        uint32_t ah[2][4], bh[4][2];
#pragma unroll
        for (int ma = 0; ma < 2; ma++) lda_frag(ah[ma], AH, warpM + ma * 16, ks, lane);
        ldb_frag(&bh[0][0], BH, warpN, ks, lane);
        ldb_frag(&bh[2][0], BH, warpN + 16, ks, lane);
#pragma unroll
        for (int ma = 0; ma < 2; ma++)
#pragma unroll
            for (int na = 0; na < 4; na++)
                mma_f16(acc[ma * 4 + na], ah[ma], bh[na]);
    }
}

__global__ __launch_bounds__(256, 3) void gemm2_h(const float* __restrict__ x,
                                                  const float* __restrict__ gamma,
                                                  float* __restrict__ out) {
    extern __shared__ uint32_t sm[];
    const uint32_t sb = smem_u32(sm);
    const int tid = threadIdx.x, lane = tid & 31, wid = tid >> 5;
    const int gid = lane >> 2, tig = lane & 3;
    const int warpM = (wid >> 2) * 32, warpN = (wid & 3) * 32;
    const int bz = blockIdx.z, by = blockIdx.y, t0 = blockIdx.x * 128;

    const uint32_t* Ah = g_ah32 + ((size_t)bz * Cn + by * 64) * 128;
    const uint32_t* Bh = g_xth32 + ((size_t)bz * Tn + t0) * 128;

    float acc[8][4];
#pragma unroll
    for (int a = 0; a < 8; a++)
#pragma unroll
        for (int c = 0; c < 4; c++) acc[a][c] = 0.f;

    auto issue = [&](int c, int s) {
        uint32_t st = sb + s * 6144 * 4;
        // A: 64 rows x 8 g = 512 transfers -> 2 per thread.
#pragma unroll
        for (int it = 0; it < 2; it++) {
            int idx = it * 256 + tid, row = idx >> 3, g = idx & 7;
            cp16(st + 4 * woff(row, g), Ah + (size_t)row * 128 + c * 32 + g * 4);
        }
        // B: 128 rows x 8 g = 1024 transfers -> 4 per thread.
#pragma unroll
        for (int it = 0; it < 4; it++) {
            int idx = it * 256 + tid, row = idx >> 3, g = idx & 7;
            cp16(st + 2048 * 4 + 4 * woff(row, g),
                 Bh + (size_t)row * 128 + c * 32 + g * 4);
        }
    };

    issue(0, 0); CP_COMMIT();
    issue(1, 1); CP_COMMIT();
    issue(2, 2); CP_COMMIT();
    CP_WAIT(2);
    __syncthreads();

    const int NC = Cn / 64;   // 4
#pragma unroll 1
    for (int c = 0; c < NC; c++) {
        g2_chunk(sb + (c % 3) * 6144 * 4, acc, warpM, warpN, lane);
        if (c + 1 < NC) {
            __syncthreads();
            if (c + 3 < NC) issue(c + 3, c % 3);
            CP_COMMIT();
            CP_WAIT(2);
            __syncthreads();
        }
    }

    const float gm = __ldg(gamma);
    const float* Xb = x + (size_t)bz * Cn * Tn;
    float* Ob = out + (size_t)bz * Cn * Tn;
#pragma unroll
    for (int ma = 0; ma < 2; ma++)
#pragma unroll
        for (int na = 0; na < 4; na++) {
            const float* d = acc[ma * 4 + na];
            int r0 = by * 64 + warpM + ma * 16 + gid;
            int cc = t0 + warpN + na * 8 + 2 * tig;
            size_t o0 = (size_t)r0 * Tn + cc;
            size_t o1 = (size_t)(r0 + 8) * Tn + cc;
            float2 x0 = *(const float2*)(Xb + o0);
            float2 x1 = *(const float2*)(Xb + o1);
            *(float2*)(Ob + o0) = make_float2(gm * d[0] + x0.x, gm * d[1] + x0.y);
            *(float2*)(Ob + o1) = make_float2(gm * d[2] + x1.x, gm * d[3] + x1.y);
        }
}

// ---------------------------------------------------------------------------
extern "C" void kernel_launch(void* const* d_in, const int* in_sizes, int n_in,
                              void* d_out, int out_size) {
    (void)in_sizes; (void)n_in; (void)out_size;
    const float* x = (const float*)d_in[0];
    const float* gamma = (const float*)d_in[1];
    float* out = (float*)d_out;

    const int smem1 = 3 * 12288 * 4;   // 144 KB
    const int smem2 = 3 * 6144 * 4;    //  72 KB (x3 CTAs/SM = 216 KB)
    cudaFuncSetAttribute(gemm1_h, cudaFuncAttributeMaxDynamicSharedMemorySize, smem1);
    cudaFuncSetAttribute(gemm2_h, cudaFuncAttributeMaxDynamicSharedMemorySize, smem2);

    split_pre<<<dim3(Tn / 64, Cn / 32, Bn), 256>>>(x);
    gemm1_h<<<dim3(Cn / 128, Cn / 128, Bn), 512, smem1>>>();
    softmax_kernel<<<Bn * Cn, 256>>>();
    gemm2_h<<<dim3(Tn / 128, Cn / 64, Bn), 256, smem2>>>(x, gamma, out);
}

// round 17
// speedup vs baseline: 1.0018x; 1.0018x over previous
#include <cuda_runtime.h>
#include <cuda_fp16.h>
#include <cstdint>

#define Bn 32
#define Cn 256
#define Tn 4096

// Static device scratch (allocation-guard legal).
__device__ float4   g_e4[(size_t)Bn * Cn * Cn / 4];      //  8 MB P = S + M (fp32)
__device__ uint32_t g_mh32[(size_t)Bn * Cn * Cn / 2];    //  4 MB M (f16)
__device__ uint32_t g_ah32[(size_t)Bn * Cn * Cn / 2];    //  4 MB attn hi (f16)
__device__ uint32_t g_xh32[(size_t)Bn * Cn * Tn / 2];    // 67 MB X hi  row-major
__device__ uint32_t g_xl32[(size_t)Bn * Cn * Tn / 2];    // 67 MB X lo  row-major
__device__ uint32_t g_xth32[(size_t)Bn * Tn * Cn / 2];   // 67 MB X^T hi

// ---------------------------------------------------------------------------
// Tile layout (proven): row = 64 k f16 = 128 B = 32 words; 16B group g at
// word offset row*32 + (g^(row&7))*4. cp.async / LDSM conflict-free.
// ---------------------------------------------------------------------------
__device__ __forceinline__ int woff(int row, int g) {
    return row * 32 + ((g ^ (row & 7)) << 2);
}
__device__ __forceinline__ uint32_t smem_u32(const void* p) {
    uint32_t a;
    asm("{ .reg .u64 t; cvta.to.shared.u64 t, %1; cvt.u32.u64 %0, t; }"
        : "=r"(a) : "l"(p));
    return a;
}
__device__ __forceinline__ uint32_t packh2(__half a, __half b) {
    return (uint32_t)__half_as_ushort(a) | ((uint32_t)__half_as_ushort(b) << 16);
}
__device__ __forceinline__ void mma_f16(float* d, const uint32_t* a, const uint32_t* b) {
    asm volatile(
        "mma.sync.aligned.m16n8k16.row.col.f32.f16.f16.f32 "
        "{%0,%1,%2,%3}, {%4,%5,%6,%7}, {%8,%9}, {%0,%1,%2,%3};"
        : "+f"(d[0]), "+f"(d[1]), "+f"(d[2]), "+f"(d[3])
        : "r"(a[0]), "r"(a[1]), "r"(a[2]), "r"(a[3]), "r"(b[0]), "r"(b[1]));
}
__device__ __forceinline__ void ldsm4(uint32_t& r0, uint32_t& r1, uint32_t& r2,
                                      uint32_t& r3, uint32_t addr) {
    asm volatile("ldmatrix.sync.aligned.m8n8.x4.shared.b16 {%0,%1,%2,%3}, [%4];"
                 : "=r"(r0), "=r"(r1), "=r"(r2), "=r"(r3) : "r"(addr));
}
__device__ __forceinline__ void lda_frag(uint32_t* a, uint32_t tb, int mrow,
                                         int ks, int lane) {
    int oct = lane >> 3, l7 = lane & 7;
    int row = mrow + ((oct & 1) << 3) + l7;
    int g = 2 * ks + (oct >> 1);
    ldsm4(a[0], a[1], a[2], a[3], tb + 4 * woff(row, g));
}
__device__ __forceinline__ void ldb_frag(uint32_t* b, uint32_t tb, int nrow,
                                         int ks, int lane) {
    int oct = lane >> 3, l7 = lane & 7;
    int row = nrow + ((oct >> 1) << 3) + l7;
    int g = 2 * ks + (oct & 1);
    ldsm4(b[0], b[1], b[2], b[3], tb + 4 * woff(row, g));
}
__device__ __forceinline__ void cp16(uint32_t saddr, const void* g) {
    asm volatile("cp.async.cg.shared.global [%0], [%1], 16;" :: "r"(saddr), "l"(g));
}
#define CP_COMMIT() asm volatile("cp.async.commit_group;" ::: "memory")
#define CP_WAIT(N)  asm volatile("cp.async.wait_group %0;" :: "n"(N) : "memory")

// ---------------------------------------------------------------------------
// Prepass (R14-proven): one read of X -> Xh (rm), Xl (rm), Xth, all f16.
// ---------------------------------------------------------------------------
__global__ __launch_bounds__(256) void split_pre(const float* __restrict__ x) {
    __shared__ __half tile[64][34];
    const int b = blockIdx.z, c0 = blockIdx.y * 32, t0 = blockIdx.x * 64;
    const int tid = threadIdx.x, cl = tid >> 5, t2 = tid & 31;
    const float* Xb = x + ((size_t)b * Cn + c0) * Tn + t0;
    uint32_t* Xh = g_xh32 + ((size_t)b * Cn + c0) * (Tn / 2) + t0 / 2;
    uint32_t* Xl = g_xl32 + ((size_t)b * Cn + c0) * (Tn / 2) + t0 / 2;
#pragma unroll
    for (int i = 0; i < 4; i++) {
        int c = cl + 8 * i;
        float2 v = *(const float2*)(Xb + (size_t)c * Tn + 2 * t2);
        __half h0 = __float2half_rn(v.x), h1 = __float2half_rn(v.y);
        Xh[(size_t)c * (Tn / 2) + t2] = packh2(h0, h1);
        Xl[(size_t)c * (Tn / 2) + t2] =
            packh2(__float2half_rn(v.x - __half2float(h0)),
                   __float2half_rn(v.y - __half2float(h1)));
        tile[2 * t2][c] = h0;
        tile[2 * t2 + 1][c] = h1;
    }
    __syncthreads();
    uint32_t* Xt = g_xth32 + ((size_t)b * Tn + t0) * (Cn / 2) + c0 / 2;
    const int tl = tid >> 4, c2 = tid & 15;
#pragma unroll
    for (int i = 0; i < 4; i++) {
        int t = tl + 16 * i;
        Xt[(size_t)t * (Cn / 2) + c2] = packh2(tile[t][2 * c2], tile[t][2 * c2 + 1]);
    }
}

// ---------------------------------------------------------------------------
// GEMM1 (symmetry trick): per tile compute S = Ah*Bh^T and M = Al*Bh^T only.
// E(i,j) = S(i,j) + M(i,j) + M(j,i) is assembled by softmax.
// CTA 128x128, 16 warps (32x32 tiles), BK=64, 3-stage cp.async.
// ---------------------------------------------------------------------------
__device__ __forceinline__ void g1_chunk(uint32_t sbase, float accS[8][4],
                                         float accM[8][4], int warpM, int warpN,
                                         int lane) {
    const uint32_t AH = sbase, AL = sbase + 4096 * 4, BH = sbase + 8192 * 4;
#pragma unroll
    for (int ks = 0; ks < 4; ks++) {
        uint32_t ah[2][4], al[2][4], bh[4][2];
#pragma unroll
        for (int ma = 0; ma < 2; ma++) lda_frag(ah[ma], AH, warpM + ma * 16, ks, lane);
#pragma unroll
        for (int ma = 0; ma < 2; ma++) lda_frag(al[ma], AL, warpM + ma * 16, ks, lane);
        ldb_frag(&bh[0][0], BH, warpN, ks, lane);
        ldb_frag(&bh[2][0], BH, warpN + 16, ks, lane);
#pragma unroll
        for (int ma = 0; ma < 2; ma++)
#pragma unroll
            for (int na = 0; na < 4; na++) {
                mma_f16(accS[ma * 4 + na], ah[ma], bh[na]);
                mma_f16(accM[ma * 4 + na], al[ma], bh[na]);
            }
    }
}

__global__ __launch_bounds__(512, 1) void gemm1_h() {
    extern __shared__ uint32_t sm[];
    const uint32_t sb = smem_u32(sm);
    const int tid = threadIdx.x, lane = tid & 31, wid = tid >> 5;
    const int gid = lane >> 2, tig = lane & 3;
    const int warpM = (wid >> 2) * 32, warpN = (wid & 3) * 32;
    const size_t pa = ((size_t)blockIdx.z * Cn + blockIdx.y * 128) * (Tn / 2);
    const size_t pb = ((size_t)blockIdx.z * Cn + blockIdx.x * 128) * (Tn / 2);
    const uint32_t* Ahp = g_xh32 + pa;
    const uint32_t* Alp = g_xl32 + pa;
    const uint32_t* Bhp = g_xh32 + pb;

    float accS[8][4], accM[8][4];
#pragma unroll
    for (int a = 0; a < 8; a++)
#pragma unroll
        for (int c = 0; c < 4; c++) { accS[a][c] = 0.f; accM[a][c] = 0.f; }

    auto issue = [&](int c, int s) {
        uint32_t st = sb + s * 12288 * 4;
#pragma unroll
        for (int it = 0; it < 2; it++) {
            int idx = it * 512 + tid, row = idx >> 3, g = idx & 7;
            int w4 = 4 * woff(row, g);
            size_t go = (size_t)row * (Tn / 2) + c * 32 + g * 4;
            cp16(st + w4, Ahp + go);
            cp16(st + 4096 * 4 + w4, Alp + go);
            cp16(st + 8192 * 4 + w4, Bhp + go);
        }
    };

    issue(0, 0); CP_COMMIT();
    issue(1, 1); CP_COMMIT();
    issue(2, 2); CP_COMMIT();
    CP_WAIT(2);
    __syncthreads();

    const int NC = Tn / 64;   // 64
#pragma unroll 1
    for (int c = 0; c < NC; c++) {
        g1_chunk(sb + (c % 3) * 12288 * 4, accS, accM, warpM, warpN, lane);
        if (c + 1 < NC) {
            __syncthreads();
            if (c + 3 < NC) issue(c + 3, c % 3);
            CP_COMMIT();
            CP_WAIT(2);
            __syncthreads();
        }
    }

    float* P = (float*)g_e4 + (size_t)blockIdx.z * Cn * Cn;
    uint32_t* Mh = g_mh32 + (size_t)blockIdx.z * Cn * Cn / 2;
#pragma unroll
    for (int ma = 0; ma < 2; ma++)
#pragma unroll
        for (int na = 0; na < 4; na++) {
            const float* s = accS[ma * 4 + na];
            const float* m = accM[ma * 4 + na];
            int r0 = blockIdx.y * 128 + warpM + ma * 16 + gid;
            int cc = blockIdx.x * 128 + warpN + na * 8 + 2 * tig;
            size_t o0 = (size_t)r0 * Cn + cc, o1 = (size_t)(r0 + 8) * Cn + cc;
            *(float2*)(P + o0) = make_float2(s[0] + m[0], s[1] + m[1]);
            *(float2*)(P + o1) = make_float2(s[2] + m[2], s[3] + m[3]);
            Mh[o0 >> 1] = packh2(__float2half_rn(m[0]), __float2half_rn(m[1]));
            Mh[o1 >> 1] = packh2(__float2half_rn(m[2]), __float2half_rn(m[3]));
        }
}

// ---------------------------------------------------------------------------
// Softmax: E(i,j) = P(i,j) + M(j,i); w = exp(min_e - e)/sum; writes f16 hi.
// ---------------------------------------------------------------------------
__global__ __launch_bounds__(256) void softmax_kernel() {
    const int row = blockIdx.x;               // b*Cn + i
    const int tid = threadIdx.x;
    const int i = row & (Cn - 1);
    const float* P = (float*)g_e4;
    const __half* Mh = (const __half*)g_mh32;

    float e = P[(size_t)row * Cn + tid] +
              __half2float(Mh[((size_t)(row - i) + tid) * Cn + i]);  // M(j=tid, i)
    float v = e;
#pragma unroll
    for (int o = 16; o; o >>= 1) v = fminf(v, __shfl_xor_sync(0xffffffffu, v, o));
    __shared__ float red[8];
    __shared__ float bc[2];
    if ((tid & 31) == 0) red[tid >> 5] = v;
    __syncthreads();
    if (tid == 0) {
        float m = red[0];
#pragma unroll
        for (int k = 1; k < 8; k++) m = fminf(m, red[k]);
        bc[0] = m;
    }
    __syncthreads();
    float p = expf(bc[0] - e);
    v = p;
#pragma unroll
    for (int o = 16; o; o >>= 1) v += __shfl_xor_sync(0xffffffffu, v, o);
    if ((tid & 31) == 0) red[tid >> 5] = v;
    __syncthreads();
    if (tid == 0) {
        float s = 0.f;
#pragma unroll
        for (int k = 0; k < 8; k++) s += red[k];
        bc[1] = 1.0f / s;
    }
    __syncthreads();
    ((__half*)g_ah32)[(size_t)row * Cn + tid] = __float2half_rn(p * bc[1]);
}

// ---------------------------------------------------------------------------
// GEMM2 (resident-A, 2 t-tiles/CTA): out = gamma*(Attn_h*X_h) + X.
// CTA m128 x (2 x n128), 8 warps (32x64 tiles), BK=64, 2 CTAs/SM.
// Smem: A resident 4 chunks x 16 KB = 64 KB; B 3-stage ring x 16 KB = 48 KB.
// B pipeline runs across the tile boundary -> tile-0 epilogue overlaps
// tile-1 B loads (the serialization R15/R16 diagnosed).
// ---------------------------------------------------------------------------
#define G2_AW 16384   // A words (4 chunks x 4096)

__device__ __forceinline__ void g2_chunk(uint32_t sbA, uint32_t sbB,
                                         float acc[16][4], int warpM, int warpN,
                                         int lane) {
#pragma unroll
    for (int ks = 0; ks < 4; ks++) {
        uint32_t ah[2][4], bh[8][2];
#pragma unroll
        for (int ma = 0; ma < 2; ma++) lda_frag(ah[ma], sbA, warpM + ma * 16, ks, lane);
#pragma unroll
        for (int p = 0; p < 4; p++) ldb_frag(&bh[2 * p][0], sbB, warpN + p * 16, ks, lane);
#pragma unroll
        for (int ma = 0; ma < 2; ma++)
#pragma unroll
            for (int na = 0; na < 8; na++)
                mma_f16(acc[ma * 8 + na], ah[ma], bh[na]);
    }
}

__global__ __launch_bounds__(256, 2) void gemm2_h(const float* __restrict__ x,
                                                  const float* __restrict__ gamma,
                                                  float* __restrict__ out) {
    extern __shared__ uint32_t sm[];
    const uint32_t sb = smem_u32(sm);
    const int tid = threadIdx.x, lane = tid & 31, wid = tid >> 5;
    const int gid = lane >> 2, tig = lane & 3;
    const int warpM = (wid >> 1) * 32, warpN = (wid & 1) * 64;
    const int bz = blockIdx.z, by = blockIdx.y, t0 = blockIdx.x * 256;

    const uint32_t* Ah = g_ah32 + ((size_t)bz * Cn + by * 128) * 128;
    const uint32_t* BhB = g_xth32 + ((size_t)bz * Tn + t0) * 128;
    const float gm = __ldg(gamma);
    const float* Xb = x + (size_t)bz * Cn * Tn;
    float* Ob = out + (size_t)bz * Cn * Tn;

    float acc[16][4];
#pragma unroll
    for (int a = 0; a < 16; a++)
#pragma unroll
        for (int c = 0; c < 4; c++) acc[a][c] = 0.f;

    // A fill: full K=256 panel, 4 chunk-tiles, 16 cp16/thread, one group.
#pragma unroll
    for (int ch = 0; ch < 4; ch++)
#pragma unroll
        for (int it = 0; it < 4; it++) {
            int idx = it * 256 + tid, row = idx >> 3, g = idx & 7;
            cp16(sb + ch * 4096 * 4 + 4 * woff(row, g),
                 Ah + (size_t)row * 128 + ch * 32 + g * 4);
        }
    CP_COMMIT();

    auto issueB = [&](int gc) {
        int tile = gc >> 2, c = gc & 3;
        uint32_t st = sb + (G2_AW + (gc % 3) * 4096) * 4;
#pragma unroll
        for (int it = 0; it < 4; it++) {
            int idx = it * 256 + tid, row = idx >> 3, g = idx & 7;
            cp16(st + 4 * woff(row, g),
                 BhB + (size_t)(tile * 128 + row) * 128 + c * 32 + g * 4);
        }
    };
    auto epilogue = [&](int tile) {
#pragma unroll
        for (int ma = 0; ma < 2; ma++)
#pragma unroll
            for (int na = 0; na < 8; na++) {
                float* d = acc[ma * 8 + na];
                int r0 = by * 128 + warpM + ma * 16 + gid;
                int cc = t0 + tile * 128 + warpN + na * 8 + 2 * tig;
                size_t o0 = (size_t)r0 * Tn + cc;
                size_t o1 = (size_t)(r0 + 8) * Tn + cc;
                float2 x0 = *(const float2*)(Xb + o0);
                float2 x1 = *(const float2*)(Xb + o1);
                *(float2*)(Ob + o0) = make_float2(gm * d[0] + x0.x, gm * d[1] + x0.y);
                *(float2*)(Ob + o1) = make_float2(gm * d[2] + x1.x, gm * d[3] + x1.y);
                d[0] = d[1] = d[2] = d[3] = 0.f;
            }
    };

    issueB(0); CP_COMMIT();
    issueB(1); CP_COMMIT();
    issueB(2); CP_COMMIT();
    CP_WAIT(2);                 // A + B0 complete
    __syncthreads();

    const int NG = 8;           // 2 tiles x 4 chunks
#pragma unroll 1
    for (int gc = 0; gc < NG; gc++) {
        g2_chunk(sb + (gc & 3) * 4096 * 4,
                 sb + (G2_AW + (gc % 3) * 4096) * 4, acc, warpM, warpN, lane);
        if (gc + 1 < NG) {
            __syncthreads();
            if (gc + 3 < NG) issueB(gc + 3);
            CP_COMMIT();
            CP_WAIT(2);
            __syncthreads();
        }
        if (gc == 3) epilogue(0);   // overlaps in-flight B loads of tile 1
    }
    epilogue(1);
}

// ---------------------------------------------------------------------------
extern "C" void kernel_launch(void* const* d_in, const int* in_sizes, int n_in,
                              void* d_out, int out_size) {
    (void)in_sizes; (void)n_in; (void)out_size;
    const float* x = (const float*)d_in[0];
    const float* gamma = (const float*)d_in[1];
    float* out = (float*)d_out;

    const int smem1 = 3 * 12288 * 4;            // 144 KB
    const int smem2 = (G2_AW + 3 * 4096) * 4;   // 112 KB (x2 CTAs/SM = 224 KB)
    cudaFuncSetAttribute(gemm1_h, cudaFuncAttributeMaxDynamicSharedMemorySize, smem1);
    cudaFuncSetAttribute(gemm2_h, cudaFuncAttributeMaxDynamicSharedMemorySize, smem2);

    split_pre<<<dim3(Tn / 64, Cn / 32, Bn), 256>>>(x);
    gemm1_h<<<dim3(Cn / 128, Cn / 128, Bn), 512, smem1>>>();
    softmax_kernel<<<Bn * Cn, 256>>>();
    gemm2_h<<<dim3(Tn / 256, Cn / 128, Bn), 256, smem2>>>(x, gamma, out);
}